// round 1
// baseline (speedup 1.0000x reference)
#include <cuda_runtime.h>

#define GRID_W 112
#define HW (GRID_W*GRID_W)
#define C 64
#define NV 512
#define NP 128
#define M (NP*NV)        /* 65536 rows */
#define IN_DIM 66
#define S 128

// Scratch (no allocations allowed)
__device__ float g_inp[(size_t)M*IN_DIM];   // step input  [M,66]
__device__ float g_h1 [(size_t)M*S];        // hidden      [M,128]
__device__ float g_polyA[(size_t)M*2];
__device__ float g_polyB[(size_t)M*2];

// ---------------------------------------------------------------------------
// Sampler: gather features at poly coords, concat poly -> inp[M,66]
// block (64,4): x = channel, y = vertex
// ---------------------------------------------------------------------------
__global__ void sample_kernel(const float* __restrict__ feature,
                              const float* __restrict__ poly,
                              float* __restrict__ inp, int step)
{
    int v = blockIdx.x * 4 + threadIdx.y;
    int c = threadIdx.x;
    int p = v >> 9;
    float px = poly[v*2+0];
    float py = poly[v*2+1];
    const float* fb = feature + (size_t)p * HW * C;
    float val;
    if (step == 0) {
        int xi = (int)fminf(fmaxf(floorf(px*GRID_W), 0.f), 111.f);
        int yi = (int)fminf(fmaxf(floorf(py*GRID_W), 0.f), 111.f);
        val = fb[(size_t)(xi + yi*GRID_W)*C + c];
    } else {
        float Xs = px*GRID_W, Ys = py*GRID_W;
        float X0 = floorf(Xs), Y0 = floorf(Ys);
        float wx = Xs - X0, wy = Ys - Y0;
        int x0 = (int)fminf(fmaxf(X0,      0.f), 111.f);
        int x1 = (int)fminf(fmaxf(X0+1.f,  0.f), 111.f);
        int y0 = (int)fminf(fmaxf(Y0,      0.f), 111.f);
        int y1 = (int)fminf(fmaxf(Y0+1.f,  0.f), 111.f);
        float m00 = fb[(size_t)(x0 + y0*GRID_W)*C + c];
        float m01 = fb[(size_t)(x0 + y1*GRID_W)*C + c];
        float m10 = fb[(size_t)(x1 + y0*GRID_W)*C + c];
        float m11 = fb[(size_t)(x1 + y1*GRID_W)*C + c];
        val = (1.f-wx)*(1.f-wy)*m00 + (1.f-wx)*wy*m01
            + wx*(1.f-wy)*m10      + wx*wy*m11;
    }
    inp[(size_t)v*IN_DIM + c] = val;
    if (c < 2) inp[(size_t)v*IN_DIM + 64 + c] = (c == 0) ? px : py;
}

// ---------------------------------------------------------------------------
// GEMM1: h1 = relu( X@W1s + ringavg(X)@W1n + b1 )    X:[M,66] -> h1:[M,128]
// Block: 64 rows x 128 cols, 256 threads (16x16), per-thread 4x8.
// Ring neighbor avg computed in SMEM with 2-row halo (wrap within polygon).
// smem: W1s[66*128] + W1n[66*128] + Xs[68*66] + Xn[64*66] = 102432 B
// ---------------------------------------------------------------------------
__global__ void __launch_bounds__(256, 2)
gemm1_kernel(const float* __restrict__ X,
             const float* __restrict__ Ws_g,
             const float* __restrict__ Wn_g,
             const float* __restrict__ b_g,
             float* __restrict__ Y)
{
    extern __shared__ float sm[];
    float* sWs = sm;                     // 66*128
    float* sWn = sWs + IN_DIM*S;         // 66*128
    float* sXs = sWn + IN_DIM*S;         // 68*66 (2-row halo top+bottom)
    float* sXn = sXs + 68*IN_DIM;        // 64*66

    const int tx = threadIdx.x, ty = threadIdx.y;
    const int tid = ty*16 + tx;
    const int r0 = blockIdx.x * 64;
    const int n0 = r0 & (NV-1);
    const int base = r0 - n0;            // polygon start row

    for (int idx = tid; idx < IN_DIM*S; idx += 256) {
        sWs[idx] = Ws_g[idx];
        sWn[idx] = Wn_g[idx];
    }
    for (int idx = tid; idx < 68*IN_DIM; idx += 256) {
        int rr = idx / IN_DIM;
        int k  = idx - rr*IN_DIM;
        int n  = (n0 + rr - 2 + NV) & (NV-1);
        sXs[idx] = X[(size_t)(base + n)*IN_DIM + k];
    }
    __syncthreads();
    for (int idx = tid; idx < 64*IN_DIM; idx += 256) {
        int i = idx / IN_DIM;
        int k = idx - i*IN_DIM;
        sXn[idx] = 0.25f * (sXs[ i     *IN_DIM + k] + sXs[(i+1)*IN_DIM + k]
                          + sXs[(i+3)*IN_DIM + k] + sXs[(i+4)*IN_DIM + k]);
    }
    __syncthreads();

    float acc[4][8];
    #pragma unroll
    for (int ii = 0; ii < 4; ii++)
        #pragma unroll
        for (int jj = 0; jj < 8; jj++)
            acc[ii][jj] = b_g[tx*8 + jj];

    const float* xrow = sXs + (2 + ty*4)*IN_DIM;
    const float* nrow = sXn + (ty*4)*IN_DIM;

    #pragma unroll 2
    for (int k = 0; k < IN_DIM; k++) {
        float xv[4], nv[4];
        #pragma unroll
        for (int ii = 0; ii < 4; ii++) {
            xv[ii] = xrow[ii*IN_DIM + k];
            nv[ii] = nrow[ii*IN_DIM + k];
        }
        float4 w0 = *(const float4*)&sWs[k*S + tx*8];
        float4 w1 = *(const float4*)&sWs[k*S + tx*8 + 4];
        float4 u0 = *(const float4*)&sWn[k*S + tx*8];
        float4 u1 = *(const float4*)&sWn[k*S + tx*8 + 4];
        #pragma unroll
        for (int ii = 0; ii < 4; ii++) {
            acc[ii][0] += xv[ii]*w0.x; acc[ii][1] += xv[ii]*w0.y;
            acc[ii][2] += xv[ii]*w0.z; acc[ii][3] += xv[ii]*w0.w;
            acc[ii][4] += xv[ii]*w1.x; acc[ii][5] += xv[ii]*w1.y;
            acc[ii][6] += xv[ii]*w1.z; acc[ii][7] += xv[ii]*w1.w;
            acc[ii][0] += nv[ii]*u0.x; acc[ii][1] += nv[ii]*u0.y;
            acc[ii][2] += nv[ii]*u0.z; acc[ii][3] += nv[ii]*u0.w;
            acc[ii][4] += nv[ii]*u1.x; acc[ii][5] += nv[ii]*u1.y;
            acc[ii][6] += nv[ii]*u1.z; acc[ii][7] += nv[ii]*u1.w;
        }
    }

    #pragma unroll
    for (int ii = 0; ii < 4; ii++) {
        int row = r0 + ty*4 + ii;
        float4 o0, o1;
        o0.x = fmaxf(acc[ii][0], 0.f); o0.y = fmaxf(acc[ii][1], 0.f);
        o0.z = fmaxf(acc[ii][2], 0.f); o0.w = fmaxf(acc[ii][3], 0.f);
        o1.x = fmaxf(acc[ii][4], 0.f); o1.y = fmaxf(acc[ii][5], 0.f);
        o1.z = fmaxf(acc[ii][6], 0.f); o1.w = fmaxf(acc[ii][7], 0.f);
        *(float4*)&Y[(size_t)row*S + tx*8]     = o0;
        *(float4*)&Y[(size_t)row*S + tx*8 + 4] = o1;
    }
}

// ---------------------------------------------------------------------------
// GEMM2 + FC + poly update:
//   h2   = relu( H@W2s + ringavg(H)@W2n + b2 )
//   pred = h2 @ Wfc + bfc
//   poly_out = poly_in + pred
// smem: Hs[68*128] + Hn[64*128] + Wt[64*128] + Fc[256] = 101376 B
// Wt reloaded 4x (W2s kb0/kb1, W2n kb0/kb1), reused as FC reduce buffer.
// ---------------------------------------------------------------------------
__global__ void __launch_bounds__(256, 2)
gemm2_kernel(const float* __restrict__ H,
             const float* __restrict__ Ws_g,
             const float* __restrict__ Wn_g,
             const float* __restrict__ b_g,
             const float* __restrict__ Wfc_g,
             const float* __restrict__ bfc_g,
             const float* __restrict__ poly_in,
             float* __restrict__ poly_out)
{
    extern __shared__ float sm[];
    float* sHs = sm;               // 68*128
    float* sHn = sHs + 68*S;       // 64*128
    float* sWt = sHn + 64*S;       // 64*128 (weight tile / reduce buffer)
    float* sFc = sWt + 64*S;       // 256

    const int tx = threadIdx.x, ty = threadIdx.y;
    const int tid = ty*16 + tx;
    const int r0 = blockIdx.x * 64;
    const int n0 = r0 & (NV-1);
    const int base = r0 - n0;

    for (int idx = tid; idx < 68*S; idx += 256) {
        int rr = idx >> 7;
        int k  = idx & 127;
        int n  = (n0 + rr - 2 + NV) & (NV-1);
        sHs[idx] = H[(size_t)(base + n)*S + k];
    }
    if (tid < 256) sFc[tid] = Wfc_g[tid];
    __syncthreads();
    for (int idx = tid; idx < 64*S; idx += 256) {
        sHn[idx] = 0.25f * (sHs[idx] + sHs[idx + S] + sHs[idx + 3*S] + sHs[idx + 4*S]);
    }

    float acc[4][8];
    #pragma unroll
    for (int ii = 0; ii < 4; ii++)
        #pragma unroll
        for (int jj = 0; jj < 8; jj++)
            acc[ii][jj] = b_g[tx*8 + jj];

    #pragma unroll 1
    for (int t = 0; t < 4; t++) {
        int phase = t >> 1;
        int kb    = t & 1;
        const float* Wg = (phase ? Wn_g : Ws_g) + kb*64*S;
        __syncthreads();
        for (int idx = tid; idx < 64*S; idx += 256) sWt[idx] = Wg[idx];
        __syncthreads();
        const float* Xb = (phase ? sHn : (sHs + 2*S)) + (ty*4)*S + kb*64;
        #pragma unroll 4
        for (int kt = 0; kt < 64; kt++) {
            float xv[4];
            #pragma unroll
            for (int ii = 0; ii < 4; ii++) xv[ii] = Xb[ii*S + kt];
            float4 w0 = *(const float4*)&sWt[kt*S + tx*8];
            float4 w1 = *(const float4*)&sWt[kt*S + tx*8 + 4];
            #pragma unroll
            for (int ii = 0; ii < 4; ii++) {
                acc[ii][0] += xv[ii]*w0.x; acc[ii][1] += xv[ii]*w0.y;
                acc[ii][2] += xv[ii]*w0.z; acc[ii][3] += xv[ii]*w0.w;
                acc[ii][4] += xv[ii]*w1.x; acc[ii][5] += xv[ii]*w1.y;
                acc[ii][6] += xv[ii]*w1.z; acc[ii][7] += xv[ii]*w1.w;
            }
        }
    }

    // relu + partial FC (over this thread's 8 columns)
    float pr[4][2];
    #pragma unroll
    for (int ii = 0; ii < 4; ii++) { pr[ii][0] = 0.f; pr[ii][1] = 0.f; }
    #pragma unroll
    for (int ii = 0; ii < 4; ii++)
        #pragma unroll
        for (int jj = 0; jj < 8; jj++) {
            float h2 = fmaxf(acc[ii][jj], 0.f);
            int c = tx*8 + jj;
            pr[ii][0] += h2 * sFc[c*2 + 0];
            pr[ii][1] += h2 * sFc[c*2 + 1];
        }

    __syncthreads();                    // done reading sWt -> reuse as reduce buf
    #pragma unroll
    for (int ii = 0; ii < 4; ii++) {
        int i = ty*4 + ii;
        sWt[i*32 + tx*2 + 0] = pr[ii][0];
        sWt[i*32 + tx*2 + 1] = pr[ii][1];
    }
    __syncthreads();
    if (tid < 128) {
        int i = tid >> 1, j = tid & 1;
        float s = 0.f;
        #pragma unroll
        for (int t = 0; t < 16; t++) s += sWt[i*32 + t*2 + j];
        s += bfc_g[j];
        int row = r0 + i;
        poly_out[(size_t)row*2 + j] = poly_in[(size_t)row*2 + j] + s;
    }
}

// ---------------------------------------------------------------------------
extern "C" void kernel_launch(void* const* d_in, const int* in_sizes, int n_in,
                              void* d_out, int out_size)
{
    const float* feature    = (const float*)d_in[0];
    const float* init_polys = (const float*)d_in[1];
    /* d_in[2] = adj: fixed ring graph, implemented as stencil */
    const float* W1s = (const float*)d_in[3];
    const float* W1n = (const float*)d_in[4];
    const float* b1  = (const float*)d_in[5];
    const float* W2s = (const float*)d_in[6];
    const float* W2n = (const float*)d_in[7];
    const float* b2  = (const float*)d_in[8];
    const float* Wfc = (const float*)d_in[9];
    const float* bfc = (const float*)d_in[10];

    cudaFuncSetAttribute(gemm1_kernel, cudaFuncAttributeMaxDynamicSharedMemorySize, 102432);
    cudaFuncSetAttribute(gemm2_kernel, cudaFuncAttributeMaxDynamicSharedMemorySize, 101376);

    float *inp, *h1, *polyA, *polyB;
    cudaGetSymbolAddress((void**)&inp,   g_inp);
    cudaGetSymbolAddress((void**)&h1,    g_h1);
    cudaGetSymbolAddress((void**)&polyA, g_polyA);
    cudaGetSymbolAddress((void**)&polyB, g_polyB);

    float* poly_out_bufs[3] = { polyA, polyB, (float*)d_out };
    const float* pin = init_polys;

    for (int i = 0; i < 3; i++) {
        sample_kernel<<<M/4, dim3(64,4)>>>(feature, pin, inp, i);
        gemm1_kernel<<<M/64, dim3(16,16), 102432>>>(
            inp, W1s + i*IN_DIM*S, W1n + i*IN_DIM*S, b1 + i*S, h1);
        gemm2_kernel<<<M/64, dim3(16,16), 101376>>>(
            h1, W2s + i*S*S, W2n + i*S*S, b2 + i*S,
            Wfc + i*S*2, bfc + i*2, pin, poly_out_bufs[i]);
        pin = poly_out_bufs[i];
    }
}

// round 4
// speedup vs baseline: 4.2446x; 4.2446x over previous
#include <cuda_runtime.h>
#include <cuda_bf16.h>
#include <cstdint>

#define GRID_W 112
#define HW (GRID_W*GRID_W)
#define NV 512
#define NP 128
#define M (NP*NV)        /* 65536 rows */
#define S 128

// ---------------------------------------------------------------------------
// Warp-level MMA helpers (sm_80+ PTX: valid for compute_103 target)
// ---------------------------------------------------------------------------
__device__ __forceinline__ uint32_t smem_u32(const void* p) {
    uint32_t a;
    asm("{ .reg .u64 t; cvta.to.shared.u64 t, %1; cvt.u32.u64 %0, t; }" : "=r"(a) : "l"(p));
    return a;
}
__device__ __forceinline__ void ldmx4(uint32_t* r, uint32_t addr) {
    asm volatile("ldmatrix.sync.aligned.m8n8.x4.shared.b16 {%0,%1,%2,%3}, [%4];"
        : "=r"(r[0]), "=r"(r[1]), "=r"(r[2]), "=r"(r[3]) : "r"(addr));
}
__device__ __forceinline__ void mma16816(float* d, const uint32_t* a,
                                         uint32_t b0, uint32_t b1) {
    asm volatile(
        "mma.sync.aligned.m16n8k16.row.col.f32.bf16.bf16.f32 "
        "{%0,%1,%2,%3}, {%4,%5,%6,%7}, {%8,%9}, {%0,%1,%2,%3};"
        : "+f"(d[0]), "+f"(d[1]), "+f"(d[2]), "+f"(d[3])
        : "r"(a[0]), "r"(a[1]), "r"(a[2]), "r"(a[3]), "r"(b0), "r"(b1));
}

// ---------------------------------------------------------------------------
// Scratch globals
// ---------------------------------------------------------------------------
__device__ __align__(16) __nv_bfloat16 g_featb[(size_t)M*64];   // sampled features
__device__ __align__(16) __nv_bfloat16 g_h1b[(size_t)M*128];    // hidden
__device__ float g_polyA[(size_t)M*2];
__device__ float g_polyB[(size_t)M*2];
__device__ __align__(16) __nv_bfloat16 g_w1sT[3*128*64];   // [step][n][k]
__device__ __align__(16) __nv_bfloat16 g_w1nT[3*128*64];
__device__ __align__(16) __nv_bfloat16 g_w2sT[3*128*128];
__device__ __align__(16) __nv_bfloat16 g_w2nT[3*128*128];
__device__ float g_pw[3*4*128];  // poly-weight rows: Ws[64],Ws[65],Wn[64],Wn[65]

// ---------------------------------------------------------------------------
// Prep: transpose + bf16-convert weights (once per launch; grid=3 steps)
// ---------------------------------------------------------------------------
__global__ void prep_kernel(const float* __restrict__ W1s, const float* __restrict__ W1n,
                            const float* __restrict__ W2s, const float* __restrict__ W2n)
{
    int i = blockIdx.x;
    int tid = threadIdx.x;
    const float* w1s = W1s + (size_t)i*66*128;
    const float* w1n = W1n + (size_t)i*66*128;
    for (int idx = tid; idx < 128*64; idx += 256) {
        int n = idx >> 6, k = idx & 63;
        g_w1sT[(size_t)i*8192 + idx] = __float2bfloat16(w1s[k*128 + n]);
        g_w1nT[(size_t)i*8192 + idx] = __float2bfloat16(w1n[k*128 + n]);
    }
    if (tid < 128) {
        g_pw[i*512 +       tid] = w1s[64*128 + tid];
        g_pw[i*512 + 128 + tid] = w1s[65*128 + tid];
        g_pw[i*512 + 256 + tid] = w1n[64*128 + tid];
        g_pw[i*512 + 384 + tid] = w1n[65*128 + tid];
    }
    const float* w2s = W2s + (size_t)i*128*128;
    const float* w2n = W2n + (size_t)i*128*128;
    for (int idx = tid; idx < 128*128; idx += 256) {
        int n = idx >> 7, k = idx & 127;
        g_w2sT[(size_t)i*16384 + idx] = __float2bfloat16(w2s[k*128 + n]);
        g_w2nT[(size_t)i*16384 + idx] = __float2bfloat16(w2n[k*128 + n]);
    }
}

// ---------------------------------------------------------------------------
// Sampler: gather features at poly coords -> g_featb [M,64] bf16
// ---------------------------------------------------------------------------
__global__ void sample_kernel(const float* __restrict__ feature,
                              const float* __restrict__ poly, int step)
{
    int v  = blockIdx.x * 8 + threadIdx.y;
    int c2 = threadIdx.x;
    int p  = v >> 9;
    float px = poly[v*2+0];
    float py = poly[v*2+1];
    const float2* fb = (const float2*)(feature + (size_t)p * HW * 64);
    float2 val;
    if (step == 0) {
        int xi = (int)fminf(fmaxf(floorf(px*GRID_W), 0.f), 111.f);
        int yi = (int)fminf(fmaxf(floorf(py*GRID_W), 0.f), 111.f);
        val = fb[(size_t)(xi + yi*GRID_W)*32 + c2];
    } else {
        float Xs = px*GRID_W, Ys = py*GRID_W;
        float X0 = floorf(Xs), Y0 = floorf(Ys);
        float wx = Xs - X0, wy = Ys - Y0;
        int x0 = (int)fminf(fmaxf(X0,     0.f), 111.f);
        int x1 = (int)fminf(fmaxf(X0+1.f, 0.f), 111.f);
        int y0 = (int)fminf(fmaxf(Y0,     0.f), 111.f);
        int y1 = (int)fminf(fmaxf(Y0+1.f, 0.f), 111.f);
        float2 m00 = fb[(size_t)(x0 + y0*GRID_W)*32 + c2];
        float2 m01 = fb[(size_t)(x0 + y1*GRID_W)*32 + c2];
        float2 m10 = fb[(size_t)(x1 + y0*GRID_W)*32 + c2];
        float2 m11 = fb[(size_t)(x1 + y1*GRID_W)*32 + c2];
        float w00 = (1.f-wx)*(1.f-wy), w01 = (1.f-wx)*wy;
        float w10 = wx*(1.f-wy),       w11 = wx*wy;
        val.x = w00*m00.x + w01*m01.x + w10*m10.x + w11*m11.x;
        val.y = w00*m00.y + w01*m01.y + w10*m10.y + w11*m11.y;
    }
    ((__nv_bfloat162*)g_featb)[(size_t)v*32 + c2] = __float22bfloat162_rn(val);
}

// ---------------------------------------------------------------------------
// GEMM1 (mma.sync): h1 = relu(X@Ws + ring(X)@Wn + poly-rank2 + b), K=64, N=128
// Block tile 128x128, 8 warps = 4(m) x 2(n), warp tile 32x64.
// Padded SMEM rows (144B = 9*16B -> conflict-free ldmatrix).
// ---------------------------------------------------------------------------
#define LDX1 144
#define S1_XS    0                       /* 132 rows x 144B (rows -2..129) */
#define S1_XN    19072                   /* 128 x 144B */
#define S1_WS    37504                   /* 128 x 144B */
#define S1_WN    55936                   /* 128 x 144B */
#define S1_PW    74368                   /* 4*128 f32 */
#define S1_BIAS  76416                   /* 128 f32 */
#define S1_POLY  76928                   /* 132*2 f32 */
#define S1_TOTAL 78080

__global__ void __launch_bounds__(256, 2)
gemm1_kernel(const float* __restrict__ poly_in, const float* __restrict__ bias_g, int step)
{
    extern __shared__ char sm[];
    uint32_t sb = smem_u32(sm);
    int tid = threadIdx.x, wid = tid >> 5, lane = tid & 31;
    int r0 = blockIdx.x * 128;
    int n0 = r0 & (NV-1);
    int pbase = r0 - n0;

    const uint4* featv = (const uint4*)g_featb;
    const uint4* wsv = (const uint4*)(g_w1sT + (size_t)step*8192);
    const uint4* wnv = (const uint4*)(g_w1nT + (size_t)step*8192);

    // X tile rows -2..129 (wrap within polygon), 8 x uint4 per row
    for (int idx = tid; idx < 132*8; idx += 256) {
        int r = idx >> 3, q = idx & 7;
        int n = (n0 + r - 2 + NV) & (NV-1);
        *(uint4*)(sm + S1_XS + r*LDX1 + q*16) = featv[(size_t)(pbase + n)*8 + q];
    }
    for (int idx = tid; idx < 128*8; idx += 256) {
        int r = idx >> 3, q = idx & 7;
        *(uint4*)(sm + S1_WS + r*LDX1 + q*16) = wsv[idx];
        *(uint4*)(sm + S1_WN + r*LDX1 + q*16) = wnv[idx];
    }
    for (int idx = tid; idx < 512; idx += 256)
        ((float*)(sm + S1_PW))[idx] = g_pw[step*512 + idx];
    if (tid < 128) ((float*)(sm + S1_BIAS))[tid] = bias_g[tid];
    for (int idx = tid; idx < 264; idx += 256) {
        int rr = idx >> 1, c = idx & 1;
        int n = (n0 + rr - 2 + NV) & (NV-1);
        ((float*)(sm + S1_POLY))[idx] = poly_in[(size_t)(pbase + n)*2 + c];
    }
    __syncthreads();

    // Xn[r] = 0.25*(X[r-2]+X[r-1]+X[r+1]+X[r+2])   (XS idx = logical+2)
    for (int w = tid; w < 128*32; w += 256) {
        int r = w >> 5, cw = w & 31;
        float sx = 0.f, sy = 0.f;
        #pragma unroll
        for (int d = 0; d < 4; d++) {
            static const int doff[4] = {0, 1, 3, 4};
            uint32_t v = *(uint32_t*)(sm + S1_XS + (r + doff[d])*LDX1 + cw*4);
            float2 f = __bfloat1622float2(*(__nv_bfloat162*)&v);
            sx += f.x; sy += f.y;
        }
        __nv_bfloat162 o = __float22bfloat162_rn(make_float2(0.25f*sx, 0.25f*sy));
        *(uint32_t*)(sm + S1_XN + r*LDX1 + cw*4) = *(uint32_t*)&o;
    }
    __syncthreads();

    int wm = wid & 3, wn = wid >> 2;
    float acc[2][8][4];
    #pragma unroll
    for (int mf = 0; mf < 2; mf++)
        #pragma unroll
        for (int nf = 0; nf < 8; nf++)
            #pragma unroll
            for (int j = 0; j < 4; j++) acc[mf][nf][j] = 0.f;

    int l7 = lane & 7, l8 = (lane >> 3) & 1, l16 = (lane >> 4) & 1;

    #pragma unroll
    for (int pass = 0; pass < 2; pass++) {
        uint32_t xbase = sb + (pass ? S1_XN : S1_XS) + (pass ? 0 : 2*LDX1);
        uint32_t wbase = sb + (pass ? S1_WN : S1_WS);
        #pragma unroll
        for (int kt = 0; kt < 4; kt++) {
            uint32_t a[2][4];
            #pragma unroll
            for (int mf = 0; mf < 2; mf++) {
                uint32_t addr = xbase + (wm*32 + mf*16 + l7 + l8*8)*LDX1 + l16*16 + kt*32;
                ldmx4(a[mf], addr);
            }
            #pragma unroll
            for (int nf2 = 0; nf2 < 4; nf2++) {
                uint32_t b[4];
                uint32_t baddr = wbase + (wn*64 + nf2*16 + l16*8 + l7)*LDX1 + kt*32 + l8*16;
                ldmx4(b, baddr);
                #pragma unroll
                for (int mf = 0; mf < 2; mf++) {
                    mma16816(acc[mf][2*nf2],   a[mf], b[0], b[1]);
                    mma16816(acc[mf][2*nf2+1], a[mf], b[2], b[3]);
                }
            }
        }
    }

    // epilogue: + bias + poly rank-2, relu, bf16 store
    const float* P  = (const float*)(sm + S1_POLY);
    const float* B  = (const float*)(sm + S1_BIAS);
    const float* PW = (const float*)(sm + S1_PW);
    int rlo = lane >> 2, qc = (lane & 3)*2;
    #pragma unroll
    for (int mf = 0; mf < 2; mf++) {
        int rb = wm*32 + mf*16 + rlo;
        float px0 = P[(rb+2)*2],  py0 = P[(rb+2)*2+1];
        float ax0 = 0.25f*(P[rb*2]   + P[(rb+1)*2]   + P[(rb+3)*2]   + P[(rb+4)*2]);
        float ay0 = 0.25f*(P[rb*2+1] + P[(rb+1)*2+1] + P[(rb+3)*2+1] + P[(rb+4)*2+1]);
        int r1 = rb + 8;
        float px1 = P[(r1+2)*2],  py1 = P[(r1+2)*2+1];
        float ax1 = 0.25f*(P[r1*2]   + P[(r1+1)*2]   + P[(r1+3)*2]   + P[(r1+4)*2]);
        float ay1 = 0.25f*(P[r1*2+1] + P[(r1+1)*2+1] + P[(r1+3)*2+1] + P[(r1+4)*2+1]);
        #pragma unroll
        for (int nf = 0; nf < 8; nf++) {
            int n = wn*64 + nf*8 + qc;
            float b0 = B[n],   w0x = PW[n],   w0y = PW[128+n],   w0ax = PW[256+n],   w0ay = PW[384+n];
            float b1 = B[n+1], w1x = PW[n+1], w1y = PW[128+n+1], w1ax = PW[256+n+1], w1ay = PW[384+n+1];
            float v00 = acc[mf][nf][0] + b0 + px0*w0x + py0*w0y + ax0*w0ax + ay0*w0ay;
            float v01 = acc[mf][nf][1] + b1 + px0*w1x + py0*w1y + ax0*w1ax + ay0*w1ay;
            float v10 = acc[mf][nf][2] + b0 + px1*w0x + py1*w0y + ax1*w0ax + ay1*w0ay;
            float v11 = acc[mf][nf][3] + b1 + px1*w1x + py1*w1y + ax1*w1ax + ay1*w1ay;
            __nv_bfloat162 h0 = __float22bfloat162_rn(make_float2(fmaxf(v00,0.f), fmaxf(v01,0.f)));
            __nv_bfloat162 h1 = __float22bfloat162_rn(make_float2(fmaxf(v10,0.f), fmaxf(v11,0.f)));
            *(uint32_t*)(g_h1b + (size_t)(r0 + rb)*128 + n) = *(uint32_t*)&h0;
            *(uint32_t*)(g_h1b + (size_t)(r0 + r1)*128 + n) = *(uint32_t*)&h1;
        }
    }
}

// ---------------------------------------------------------------------------
// GEMM2 (mma.sync): h2 = relu(H@Ws + ring(H)@Wn + b); pred = h2@Wfc + bfc;
// poly_out = poly_in + pred.  K=128, padded rows 272B (17*16B).
// Two-pass weight staging (Ws then Wn) to fit 2 CTAs/SM.
// ---------------------------------------------------------------------------
#define LDX2 272
#define S2_HS    0                       /* 132 x 272 */
#define S2_HN    35968                   /* 128 x 272 */
#define S2_W     70784                   /* 128 x 272 */
#define S2_FC    105600                  /* 128*2 f32 */
#define S2_BIAS  106624                  /* 128 f32 */
#define S2_POLY  107136                  /* 128*2 f32 */
#define S2_RED   108160                  /* 128*4 f32 */
#define S2_TOTAL 110208

__global__ void __launch_bounds__(256, 2)
gemm2_kernel(const float* __restrict__ poly_in,
             float* __restrict__ poly_out,
             const float* __restrict__ bias_g,
             const float* __restrict__ wfc_g,
             const float* __restrict__ bfc_g,
             int step)
{
    extern __shared__ char sm[];
    uint32_t sb = smem_u32(sm);
    int tid = threadIdx.x, wid = tid >> 5, lane = tid & 31;
    int r0 = blockIdx.x * 128;
    int n0 = r0 & (NV-1);
    int pbase = r0 - n0;

    const uint4* h1v = (const uint4*)g_h1b;
    const uint4* wsv = (const uint4*)(g_w2sT + (size_t)step*16384);
    const uint4* wnv = (const uint4*)(g_w2nT + (size_t)step*16384);

    for (int idx = tid; idx < 132*16; idx += 256) {
        int r = idx >> 4, q = idx & 15;
        int n = (n0 + r - 2 + NV) & (NV-1);
        *(uint4*)(sm + S2_HS + r*LDX2 + q*16) = h1v[(size_t)(pbase + n)*16 + q];
    }
    for (int idx = tid; idx < 128*16; idx += 256) {
        int r = idx >> 4, q = idx & 15;
        *(uint4*)(sm + S2_W + r*LDX2 + q*16) = wsv[idx];
    }
    if (tid < 256) {
        ((float*)(sm + S2_FC))[tid]   = wfc_g[tid];
        ((float*)(sm + S2_POLY))[tid] = poly_in[(size_t)r0*2 + tid];
    }
    if (tid < 128) ((float*)(sm + S2_BIAS))[tid] = bias_g[tid];
    __syncthreads();

    // Hn stencil
    for (int w = tid; w < 128*64; w += 256) {
        int r = w >> 6, cw = w & 63;
        float sx = 0.f, sy = 0.f;
        #pragma unroll
        for (int d = 0; d < 4; d++) {
            static const int doff[4] = {0, 1, 3, 4};
            uint32_t v = *(uint32_t*)(sm + S2_HS + (r + doff[d])*LDX2 + cw*4);
            float2 f = __bfloat1622float2(*(__nv_bfloat162*)&v);
            sx += f.x; sy += f.y;
        }
        __nv_bfloat162 o = __float22bfloat162_rn(make_float2(0.25f*sx, 0.25f*sy));
        *(uint32_t*)(sm + S2_HN + r*LDX2 + cw*4) = *(uint32_t*)&o;
    }
    __syncthreads();

    int wm = wid & 3, wn = wid >> 2;
    int l7 = lane & 7, l8 = (lane >> 3) & 1, l16 = (lane >> 4) & 1;
    float acc[2][8][4];
    #pragma unroll
    for (int mf = 0; mf < 2; mf++)
        #pragma unroll
        for (int nf = 0; nf < 8; nf++)
            #pragma unroll
            for (int j = 0; j < 4; j++) acc[mf][nf][j] = 0.f;

    for (int pass = 0; pass < 2; pass++) {
        if (pass == 1) {
            __syncthreads();   // all warps done reading W (Ws)
            for (int idx = tid; idx < 128*16; idx += 256) {
                int r = idx >> 4, q = idx & 15;
                *(uint4*)(sm + S2_W + r*LDX2 + q*16) = wnv[idx];
            }
            __syncthreads();
        }
        uint32_t xbase = sb + (pass ? S2_HN : (S2_HS + 2*LDX2));
        uint32_t wbase = sb + S2_W;
        #pragma unroll
        for (int kt = 0; kt < 8; kt++) {
            uint32_t a[2][4];
            #pragma unroll
            for (int mf = 0; mf < 2; mf++) {
                uint32_t addr = xbase + (wm*32 + mf*16 + l7 + l8*8)*LDX2 + l16*16 + kt*32;
                ldmx4(a[mf], addr);
            }
            #pragma unroll
            for (int nf2 = 0; nf2 < 4; nf2++) {
                uint32_t b[4];
                uint32_t baddr = wbase + (wn*64 + nf2*16 + l16*8 + l7)*LDX2 + kt*32 + l8*16;
                ldmx4(b, baddr);
                #pragma unroll
                for (int mf = 0; mf < 2; mf++) {
                    mma16816(acc[mf][2*nf2],   a[mf], b[0], b[1]);
                    mma16816(acc[mf][2*nf2+1], a[mf], b[2], b[3]);
                }
            }
        }
    }

    // epilogue: relu(acc+bias) -> FC(128->2) partial sums
    const float* B  = (const float*)(sm + S2_BIAS);
    const float* FC = (const float*)(sm + S2_FC);
    int rlo = lane >> 2, qc = (lane & 3)*2;
    float pr[2][2][2];
    #pragma unroll
    for (int mf = 0; mf < 2; mf++)
        #pragma unroll
        for (int rh = 0; rh < 2; rh++) { pr[mf][rh][0] = 0.f; pr[mf][rh][1] = 0.f; }

    #pragma unroll
    for (int mf = 0; mf < 2; mf++)
        #pragma unroll
        for (int nf = 0; nf < 8; nf++) {
            int n = wn*64 + nf*8 + qc;
            float b0 = B[n], b1 = B[n+1];
            float h00 = fmaxf(acc[mf][nf][0] + b0, 0.f);
            float h01 = fmaxf(acc[mf][nf][1] + b1, 0.f);
            float h10 = fmaxf(acc[mf][nf][2] + b0, 0.f);
            float h11 = fmaxf(acc[mf][nf][3] + b1, 0.f);
            float f0x = FC[n*2], f0y = FC[n*2+1], f1x = FC[(n+1)*2], f1y = FC[(n+1)*2+1];
            pr[mf][0][0] += h00*f0x + h01*f1x;  pr[mf][0][1] += h00*f0y + h01*f1y;
            pr[mf][1][0] += h10*f0x + h11*f1x;  pr[mf][1][1] += h10*f0y + h11*f1y;
        }
    #pragma unroll
    for (int mf = 0; mf < 2; mf++)
        #pragma unroll
        for (int rh = 0; rh < 2; rh++)
            #pragma unroll
            for (int j = 0; j < 2; j++) {
                pr[mf][rh][j] += __shfl_xor_sync(0xffffffffu, pr[mf][rh][j], 1);
                pr[mf][rh][j] += __shfl_xor_sync(0xffffffffu, pr[mf][rh][j], 2);
            }
    float* RED = (float*)(sm + S2_RED);
    if ((lane & 3) == 0) {
        #pragma unroll
        for (int mf = 0; mf < 2; mf++)
            #pragma unroll
            for (int rh = 0; rh < 2; rh++) {
                int row = wm*32 + mf*16 + rh*8 + rlo;
                RED[row*4 + wn*2 + 0] = pr[mf][rh][0];
                RED[row*4 + wn*2 + 1] = pr[mf][rh][1];
            }
    }
    __syncthreads();
    {
        int row = tid >> 1, j = tid & 1;
        float s = RED[row*4 + j] + RED[row*4 + 2 + j] + bfc_g[j];
        poly_out[(size_t)(r0 + row)*2 + j] = ((const float*)(sm + S2_POLY))[row*2 + j] + s;
    }
}

// ---------------------------------------------------------------------------
extern "C" void kernel_launch(void* const* d_in, const int* in_sizes, int n_in,
                              void* d_out, int out_size)
{
    const float* feature    = (const float*)d_in[0];
    const float* init_polys = (const float*)d_in[1];
    /* d_in[2] = adj (fixed ring graph -> stencil) */
    const float* W1s = (const float*)d_in[3];
    const float* W1n = (const float*)d_in[4];
    const float* b1  = (const float*)d_in[5];
    const float* W2s = (const float*)d_in[6];
    const float* W2n = (const float*)d_in[7];
    const float* b2  = (const float*)d_in[8];
    const float* Wfc = (const float*)d_in[9];
    const float* bfc = (const float*)d_in[10];

    cudaFuncSetAttribute(gemm1_kernel, cudaFuncAttributeMaxDynamicSharedMemorySize, S1_TOTAL);
    cudaFuncSetAttribute(gemm2_kernel, cudaFuncAttributeMaxDynamicSharedMemorySize, S2_TOTAL);

    float *polyA, *polyB;
    cudaGetSymbolAddress((void**)&polyA, g_polyA);
    cudaGetSymbolAddress((void**)&polyB, g_polyB);

    prep_kernel<<<3, 256>>>(W1s, W1n, W2s, W2n);

    float* pouts[3] = { polyA, polyB, (float*)d_out };
    const float* pin = init_polys;
    for (int i = 0; i < 3; i++) {
        sample_kernel<<<M/8, dim3(32,8)>>>(feature, pin, i);
        gemm1_kernel<<<M/128, 256, S1_TOTAL>>>(pin, b1 + i*S, i);
        gemm2_kernel<<<M/128, 256, S2_TOTAL>>>(pin, pouts[i], b2 + i*S,
                                               Wfc + i*S*2, bfc + i*2, i);
        pin = pouts[i];
    }
}